// round 8
// baseline (speedup 1.0000x reference)
#include <cuda_runtime.h>
#include <cstdint>

#define N_TX   500000
#define N_ACC  100000
#define NE     1000000

#define SCAN_BS   1024
#define N_SCAN_BLKS ((N_TX + SCAN_BS - 1) / SCAN_BS)   // 489

// CSR scratch
__device__ int g_deg[N_TX];
__device__ int g_off[N_TX];
__device__ int g_sorted_src[NE];
__device__ int g_bsum[SCAN_BS];

// ---------------------------------------------------------------------------
__global__ void zero_kernel() {
    int i = blockIdx.x * blockDim.x + threadIdx.x;
    if (i < N_TX) g_deg[i] = 0;
}

__global__ void hist_kernel(const int* __restrict__ dst_idx) {
    int e = blockIdx.x * blockDim.x + threadIdx.x;
    if (e < NE) atomicAdd(&g_deg[dst_idx[e]], 1);
}

__global__ void scan1_kernel() {
    __shared__ int sh[SCAN_BS];
    int t = threadIdx.x;
    int idx = blockIdx.x * SCAN_BS + t;
    int v = (idx < N_TX) ? g_deg[idx] : 0;
    sh[t] = v;
    __syncthreads();
    #pragma unroll
    for (int o = 1; o < SCAN_BS; o <<= 1) {
        int add = (t >= o) ? sh[t - o] : 0;
        __syncthreads();
        sh[t] += add;
        __syncthreads();
    }
    if (idx < N_TX) g_off[idx] = sh[t] - v;
    if (t == SCAN_BS - 1) g_bsum[blockIdx.x] = sh[t];
}

__global__ void scan2_kernel() {
    __shared__ int sh[SCAN_BS];
    int t = threadIdx.x;
    int v = (t < N_SCAN_BLKS) ? g_bsum[t] : 0;
    sh[t] = v;
    __syncthreads();
    #pragma unroll
    for (int o = 1; o < SCAN_BS; o <<= 1) {
        int add = (t >= o) ? sh[t - o] : 0;
        __syncthreads();
        sh[t] += add;
        __syncthreads();
    }
    if (t < N_SCAN_BLKS) g_bsum[t] = sh[t] - v;
}

__global__ void place_kernel(const int* __restrict__ src_idx,
                             const int* __restrict__ dst_idx) {
    int e = blockIdx.x * blockDim.x + threadIdx.x;
    if (e >= NE) return;
    int d = dst_idx[e];
    int pos = atomicAdd(&g_off[d], 1) + g_bsum[d >> 10];
    g_sorted_src[pos] = src_idx[e];
}

// ---------------------------------------------------------------------------
// Fused compute kernel, 256 threads / 128 rows.
// A stored K-major: A_T[48 kp][132] bf16x2 hi/lo; B[48 kp][68] hi/lo.
// Warp w computes the m16 tile rows [w*16, w*16+16).
// ---------------------------------------------------------------------------
#define RBLK    128
#define THREADS 256
#define AT_S    132   // 132 % 32 == 4 -> frag bank = 4t + g, bijective
#define B_STR   68    // 68  % 32 == 4 -> frag bank = 4t + g (+8nt), bijective
#define H_STR   68    // restage stride (floats)

// dynamic smem (u32): AhiT | AloT | Bh | Bl
#define SM_AHI 0
#define SM_ALO (48 * AT_S)                    // 6336
#define SM_BH  (SM_ALO + 48 * AT_S)           // 12672
#define SM_BL  (SM_BH + 48 * B_STR)           // 15936
#define SM_TOT (SM_BL + 48 * B_STR)           // 19200 u32
#define SMEM_BYTES (SM_TOT * 4)               // 76800 B

// pack two f32 into bf16x2 hi + residual lo (v0 -> low half = even k)
__device__ __forceinline__ void pack_pair(float v0, float v1,
                                          uint32_t& hi, uint32_t& lo) {
    uint32_t h;
    asm("cvt.rn.bf16x2.f32 %0, %1, %2;" : "=r"(h) : "f"(v1), "f"(v0));
    float f0 = __uint_as_float(h << 16);
    float f1 = __uint_as_float(h & 0xffff0000u);
    float r0 = v0 - f0, r1 = v1 - f1;
    uint32_t l;
    asm("cvt.rn.bf16x2.f32 %0, %1, %2;" : "=r"(l) : "f"(r1), "f"(r0));
    hi = h; lo = l;
}

__device__ __forceinline__ void mma16(float* c, const uint32_t* a, const uint32_t* b) {
    asm volatile(
        "mma.sync.aligned.m16n8k16.row.col.f32.bf16.bf16.f32 "
        "{%0,%1,%2,%3}, {%4,%5,%6,%7}, {%8,%9}, {%0,%1,%2,%3};"
        : "+f"(c[0]), "+f"(c[1]), "+f"(c[2]), "+f"(c[3])
        : "r"(a[0]), "r"(a[1]), "r"(a[2]), "r"(a[3]), "r"(b[0]), "r"(b[1]));
}

__global__ void __launch_bounds__(THREADS, 2)
compute_kernel(const float* __restrict__ x_tx,
               const float* __restrict__ x_acc,
               const float* __restrict__ Wl,   // [32,64]
               const float* __restrict__ bl,   // [64]
               const float* __restrict__ Wr,   // [64,64]
               const float* __restrict__ Wout, // [64]
               const float* __restrict__ bout, // [1]
               float* __restrict__ out) {
    extern __shared__ uint32_t smem_u32[];
    uint32_t* Ahi = smem_u32 + SM_AHI;
    uint32_t* Alo = smem_u32 + SM_ALO;
    uint32_t* Bh  = smem_u32 + SM_BH;
    uint32_t* Blo = smem_u32 + SM_BL;
    float* restage = (float*)smem_u32;   // reused after GEMM
    __shared__ float bl_s[64];
    __shared__ float wout_s[64];

    const int tid  = threadIdx.x;
    const int wid  = tid >> 5;
    const int lane = tid & 31;
    const int r0   = blockIdx.x * RBLK;

    if (tid < 64) { bl_s[tid] = bl[tid]; wout_s[tid] = Wout[tid]; }

    // ---- Stage A: 2 threads per row; thread covers dims [half*32, half*32+32)
    //      of x_tx (kp half*16 .. +16) and dims [half*16, half*16+16) of agg
    //      (kp 32 + half*8 .. +8).
    {
        const int row  = tid >> 1;
        const int half = tid & 1;
        const int r    = r0 + row;

        if (r < N_TX) {
            const float4* xr = (const float4*)(x_tx + (size_t)r * 64) + half * 8;
            #pragma unroll
            for (int j = 0; j < 8; j++) {
                float4 v = xr[j];
                uint32_t h0, l0, h1, l1;
                pack_pair(v.x, v.y, h0, l0);
                pack_pair(v.z, v.w, h1, l1);
                int kp = half * 16 + j * 2;
                Ahi[kp * AT_S + row] = h0; Ahi[(kp + 1) * AT_S + row] = h1;
                Alo[kp * AT_S + row] = l0; Alo[(kp + 1) * AT_S + row] = l1;
            }
        } else {
            #pragma unroll
            for (int j = 0; j < 16; j++) {
                int kp = half * 16 + j;
                Ahi[kp * AT_S + row] = 0u;
                Alo[kp * AT_S + row] = 0u;
            }
        }

        // CSR gather-mean over this thread's 16 agg dims
        float a[16];
        #pragma unroll
        for (int d = 0; d < 16; d++) a[d] = 0.f;
        int cnt = 0;
        if (r < N_TX) {
            cnt = g_deg[r];
            int end = g_off[r] + g_bsum[r >> 10];
            int start = end - cnt;
            for (int i = 0; i < cnt; i++) {
                int s = g_sorted_src[start + i];
                const float4* p = (const float4*)(x_acc + (size_t)s * 32) + half * 4;
                #pragma unroll
                for (int j = 0; j < 4; j++) {
                    float4 v = p[j];
                    a[j * 4 + 0] += v.x; a[j * 4 + 1] += v.y;
                    a[j * 4 + 2] += v.z; a[j * 4 + 3] += v.w;
                }
            }
        }
        float inv = 1.f / (float)max(cnt, 1);
        #pragma unroll
        for (int m = 0; m < 8; m++) {
            uint32_t h, l;
            pack_pair(a[2 * m] * inv, a[2 * m + 1] * inv, h, l);
            int kp = 32 + half * 8 + m;
            Ahi[kp * AT_S + row] = h;
            Alo[kp * AT_S + row] = l;
        }
    }

    // ---- Stage B = W^T [96 k][64 n] as bf16x2 k-pairs, hi/lo ----
    {
        const int n   = tid & 63;
        const int kp0 = (tid >> 6) * 12;   // 4 quarters x 12 kp
        for (int kp = kp0; kp < kp0 + 12; kp++) {
            int k0 = kp * 2, k1 = kp * 2 + 1;
            float w0 = (k0 < 64) ? Wr[k0 * 64 + n] : Wl[(k0 - 64) * 64 + n];
            float w1 = (k1 < 64) ? Wr[k1 * 64 + n] : Wl[(k1 - 64) * 64 + n];
            uint32_t h, l;
            pack_pair(w0, w1, h, l);
            Bh[kp * B_STR + n]  = h;
            Blo[kp * B_STR + n] = l;
        }
    }
    __syncthreads();

    const int t  = lane & 3;
    const int g  = lane >> 2;
    const int rw = wid * 16;   // warp's m16 tile row base

    // Accumulators [ntile][4], seeded with bias
    float acc[8][4];
    #pragma unroll
    for (int nt = 0; nt < 8; nt++) {
        float b0 = bl_s[nt * 8 + t * 2];
        float b1 = bl_s[nt * 8 + t * 2 + 1];
        acc[nt][0] = b0; acc[nt][1] = b1;
        acc[nt][2] = b0; acc[nt][3] = b1;
    }

    #pragma unroll
    for (int kt = 0; kt < 6; kt++) {
        const int kp0 = kt * 8;
        const uint32_t* Ah = Ahi + (kp0 + t) * AT_S + rw + g;
        const uint32_t* Al = Alo + (kp0 + t) * AT_S + rw + g;
        uint32_t ahi[4], alo[4];
        ahi[0] = Ah[0];                 // (row g,   kp t)
        ahi[1] = Ah[8];                 // (row g+8, kp t)
        ahi[2] = Ah[4 * AT_S];          // (row g,   kp t+4)
        ahi[3] = Ah[4 * AT_S + 8];      // (row g+8, kp t+4)
        alo[0] = Al[0];
        alo[1] = Al[8];
        alo[2] = Al[4 * AT_S];
        alo[3] = Al[4 * AT_S + 8];
        #pragma unroll
        for (int nt = 0; nt < 8; nt++) {
            const uint32_t* Bp = Bh  + (kp0 + t) * B_STR + nt * 8 + g;
            const uint32_t* Lp = Blo + (kp0 + t) * B_STR + nt * 8 + g;
            uint32_t bh[2], blv[2];
            bh[0]  = Bp[0];
            bh[1]  = Bp[4 * B_STR];
            blv[0] = Lp[0];
            blv[1] = Lp[4 * B_STR];
            mma16(acc[nt], ahi, bh);
            mma16(acc[nt], alo, bh);
            mma16(acc[nt], ahi, blv);
        }
    }
    __syncthreads();   // done reading A/B; reuse smem as restage buffer

    // ---- Epilogue: relu + logit dot + restage ----
    #pragma unroll
    for (int hh = 0; hh < 2; hh++) {
        const int row = rw + hh * 8 + g;
        float* hrow = restage + row * H_STR;
        float partial = 0.f;
        #pragma unroll
        for (int nt = 0; nt < 8; nt++) {
            float h0 = fmaxf(acc[nt][hh * 2 + 0], 0.f);
            float h1 = fmaxf(acc[nt][hh * 2 + 1], 0.f);
            int col = nt * 8 + t * 2;
            partial += h0 * wout_s[col] + h1 * wout_s[col + 1];
            *(float2*)(hrow + col) = make_float2(h0, h1);
        }
        partial += __shfl_xor_sync(0xffffffffu, partial, 1);
        partial += __shfl_xor_sync(0xffffffffu, partial, 2);
        int r = r0 + row;
        if (t == 0 && r < N_TX) out[r] = partial + bout[0];
    }
    __syncthreads();

    // ---- Coalesced tx_x store ----
    {
        const int vr = (N_TX - r0 < RBLK) ? (N_TX - r0) : RBLK;
        float4* dst = (float4*)(out + N_TX + (size_t)r0 * 64);
        #pragma unroll
        for (int i = tid; i < RBLK * 16; i += THREADS) {
            int row = i >> 4, c = i & 15;
            if (row < vr)
                dst[row * 16 + c] = *(float4*)(restage + row * H_STR + c * 4);
        }
    }
}

// ---------------------------------------------------------------------------
extern "C" void kernel_launch(void* const* d_in, const int* in_sizes, int n_in,
                              void* d_out, int out_size) {
    const float* x_tx     = (const float*)d_in[0];
    const float* x_acc    = (const float*)d_in[1];
    const int*   pays_src = (const int*)d_in[2];
    const int*   pays_dst = (const int*)d_in[3];
    // d_in[4], d_in[5]: rev edges — dead code in reference (h_acc unused)
    const float* Wl_pays  = (const float*)d_in[6];
    const float* bl_pays  = (const float*)d_in[7];
    const float* Wr_pays  = (const float*)d_in[8];
    // d_in[9..11]: rev weights — unused
    const float* W_out    = (const float*)d_in[12];
    const float* b_out    = (const float*)d_in[13];
    float* out = (float*)d_out;   // [logits(500000) | tx_x(500000*64)]

    cudaFuncSetAttribute(compute_kernel,
                         cudaFuncAttributeMaxDynamicSharedMemorySize, SMEM_BYTES);

    zero_kernel<<<(N_TX + 255) / 256, 256>>>();
    hist_kernel<<<(NE + 255) / 256, 256>>>(pays_dst);
    scan1_kernel<<<N_SCAN_BLKS, SCAN_BS>>>();
    scan2_kernel<<<1, SCAN_BS>>>();
    place_kernel<<<(NE + 255) / 256, 256>>>(pays_src, pays_dst);
    compute_kernel<<<(N_TX + RBLK - 1) / RBLK, THREADS, SMEM_BYTES>>>(
        x_tx, x_acc, Wl_pays, bl_pays, Wr_pays, W_out, b_out, out);
}

// round 9
// speedup vs baseline: 1.1112x; 1.1112x over previous
#include <cuda_runtime.h>
#include <cstdint>

#define N_TX   500000
#define N_ACC  100000
#define NE     1000000

#define SCAN_BS   1024
#define N_SCAN_BLKS ((N_TX + SCAN_BS - 1) / SCAN_BS)   // 489

// CSR scratch
__device__ int g_deg[N_TX];
__device__ int g_off[N_TX];      // local-exclusive offsets; bumped by place
__device__ int g_sorted_src[NE];
__device__ int g_bsum[SCAN_BS];

// ---------------------------------------------------------------------------
__global__ void zero_kernel() {
    int i = blockIdx.x * blockDim.x + threadIdx.x;
    if (i < N_TX) g_deg[i] = 0;
}

__global__ void hist_kernel(const int* __restrict__ dst_idx) {
    int e = blockIdx.x * blockDim.x + threadIdx.x;
    if (e < NE) atomicAdd(&g_deg[dst_idx[e]], 1);
}

__global__ void scan1_kernel() {
    __shared__ int sh[SCAN_BS];
    int t = threadIdx.x;
    int idx = blockIdx.x * SCAN_BS + t;
    int v = (idx < N_TX) ? g_deg[idx] : 0;
    sh[t] = v;
    __syncthreads();
    #pragma unroll
    for (int o = 1; o < SCAN_BS; o <<= 1) {
        int add = (t >= o) ? sh[t - o] : 0;
        __syncthreads();
        sh[t] += add;
        __syncthreads();
    }
    if (idx < N_TX) g_off[idx] = sh[t] - v;
    if (t == SCAN_BS - 1) g_bsum[blockIdx.x] = sh[t];
}

__global__ void scan2_kernel() {
    __shared__ int sh[SCAN_BS];
    int t = threadIdx.x;
    int v = (t < N_SCAN_BLKS) ? g_bsum[t] : 0;
    sh[t] = v;
    __syncthreads();
    #pragma unroll
    for (int o = 1; o < SCAN_BS; o <<= 1) {
        int add = (t >= o) ? sh[t - o] : 0;
        __syncthreads();
        sh[t] += add;
        __syncthreads();
    }
    if (t < N_SCAN_BLKS) g_bsum[t] = sh[t] - v;
}

__global__ void place_kernel(const int* __restrict__ src_idx,
                             const int* __restrict__ dst_idx) {
    int e = blockIdx.x * blockDim.x + threadIdx.x;
    if (e >= NE) return;
    int d = dst_idx[e];
    int pos = atomicAdd(&g_off[d], 1) + g_bsum[d >> 10];
    g_sorted_src[pos] = src_idx[e];
}

// ---------------------------------------------------------------------------
// Fused compute kernel (R7 structure): CSR gather-mean + [x|agg][128x96] @
// W^T[96x64] via mma.sync m16n8k16 bf16 hi/lo 3-product; relu + logit head.
// 128 threads, 4 warps, warp = 32 rows (2 m16 tiles).
// Streaming data (x_tx reads, output writes, CSR edge stream) uses
// evict-first cache ops so the 12.8 MB x_acc table stays L2-resident.
// ---------------------------------------------------------------------------
#define RBLK   128
#define A_STR  52    // u32/row (need >=48). 52%32==20 -> frag bank=(20g+t): bijective
#define B_STR  72    // u32; 72%32==8 -> frag bank = 8t+g, bijective
#define H_STR  68    // restage stride (floats)

// dynamic smem (u32 units): Ahi | Alo | Bh | Bl
#define SM_AHI 0
#define SM_ALO (RBLK * A_STR)                 // 6656
#define SM_BH  (SM_ALO + RBLK * A_STR)        // 13312
#define SM_BL  (SM_BH + 48 * B_STR)           // 16768
#define SM_TOT (SM_BL + 48 * B_STR)           // 20224 u32
#define SMEM_BYTES (SM_TOT * 4)               // 80896 B

// pack two f32 into bf16x2 hi + residual lo (v0 -> low half = even k)
__device__ __forceinline__ void pack_pair(float v0, float v1,
                                          uint32_t& hi, uint32_t& lo) {
    uint32_t h;
    asm("cvt.rn.bf16x2.f32 %0, %1, %2;" : "=r"(h) : "f"(v1), "f"(v0));
    float f0 = __uint_as_float(h << 16);
    float f1 = __uint_as_float(h & 0xffff0000u);
    float r0 = v0 - f0, r1 = v1 - f1;
    uint32_t l;
    asm("cvt.rn.bf16x2.f32 %0, %1, %2;" : "=r"(l) : "f"(r1), "f"(r0));
    hi = h; lo = l;
}

__device__ __forceinline__ void mma16(float* c, const uint32_t* a, const uint32_t* b) {
    asm volatile(
        "mma.sync.aligned.m16n8k16.row.col.f32.bf16.bf16.f32 "
        "{%0,%1,%2,%3}, {%4,%5,%6,%7}, {%8,%9}, {%0,%1,%2,%3};"
        : "+f"(c[0]), "+f"(c[1]), "+f"(c[2]), "+f"(c[3])
        : "r"(a[0]), "r"(a[1]), "r"(a[2]), "r"(a[3]), "r"(b[0]), "r"(b[1]));
}

__global__ void __launch_bounds__(128, 2)
compute_kernel(const float* __restrict__ x_tx,
               const float* __restrict__ x_acc,
               const float* __restrict__ Wl,   // [32,64]
               const float* __restrict__ bl,   // [64]
               const float* __restrict__ Wr,   // [64,64]
               const float* __restrict__ Wout, // [64]
               const float* __restrict__ bout, // [1]
               float* __restrict__ out) {
    extern __shared__ uint32_t smem_u32[];
    uint32_t* Ahi = smem_u32 + SM_AHI;
    uint32_t* Alo = smem_u32 + SM_ALO;
    uint32_t* Bh  = smem_u32 + SM_BH;
    uint32_t* Blo = smem_u32 + SM_BL;
    float* restage = (float*)smem_u32;   // reused after GEMM
    __shared__ float bl_s[64];
    __shared__ float wout_s[64];

    const int tid  = threadIdx.x;
    const int wid  = tid >> 5;
    const int lane = tid & 31;
    const int r0   = blockIdx.x * RBLK;

    if (tid < 64) { bl_s[tid] = bl[tid]; wout_s[tid] = Wout[tid]; }

    // ---- Stage A row (thread = row): x_tx -> kp 0..31, agg -> kp 32..47 ----
    {
        const int r = r0 + tid;
        uint32_t* AhiR = Ahi + tid * A_STR;
        uint32_t* AloR = Alo + tid * A_STR;

        if (r < N_TX) {
            const float4* xr = (const float4*)(x_tx + (size_t)r * 64);
            #pragma unroll
            for (int j = 0; j < 16; j++) {
                float4 v = __ldcs(xr + j);   // streaming: read-once
                uint32_t h0, l0, h1, l1;
                pack_pair(v.x, v.y, h0, l0);
                pack_pair(v.z, v.w, h1, l1);
                AhiR[j * 2] = h0; AhiR[j * 2 + 1] = h1;
                AloR[j * 2] = l0; AloR[j * 2 + 1] = l1;
            }
        } else {
            #pragma unroll
            for (int j = 0; j < 32; j++) { AhiR[j] = 0u; AloR[j] = 0u; }
        }

        // CSR gather-mean (x_acc loads use the DEFAULT policy -> stay in L2)
        float a[32];
        #pragma unroll
        for (int d = 0; d < 32; d++) a[d] = 0.f;
        int cnt = 0;
        if (r < N_TX) {
            cnt = g_deg[r];
            int end = g_off[r] + g_bsum[r >> 10];
            int start = end - cnt;
            for (int i = 0; i < cnt; i++) {
                int s = __ldcs(g_sorted_src + start + i);   // edge stream: read-once
                const float4* p = (const float4*)(x_acc + (size_t)s * 32);
                #pragma unroll
                for (int j = 0; j < 8; j++) {
                    float4 v = p[j];
                    a[j * 4 + 0] += v.x; a[j * 4 + 1] += v.y;
                    a[j * 4 + 2] += v.z; a[j * 4 + 3] += v.w;
                }
            }
        }
        float inv = 1.f / (float)max(cnt, 1);
        #pragma unroll
        for (int j = 0; j < 16; j++) {
            uint32_t h, l;
            pack_pair(a[j * 2] * inv, a[j * 2 + 1] * inv, h, l);
            AhiR[32 + j] = h;
            AloR[32 + j] = l;
        }
    }

    // ---- Stage B = W^T [96 k][64 n] as bf16x2 k-pairs, hi/lo ----
    {
        const int n   = tid & 63;
        const int kp0 = (tid >> 6) * 24;   // 24 k-pairs per half
        for (int kp = kp0; kp < kp0 + 24; kp++) {
            int k0 = kp * 2;
            float w0 = (k0 < 64) ? Wr[k0 * 64 + n] : Wl[(k0 - 64) * 64 + n];
            int k1 = k0 + 1;
            float w1 = (k1 < 64) ? Wr[k1 * 64 + n] : Wl[(k1 - 64) * 64 + n];
            uint32_t h, l;
            pack_pair(w0, w1, h, l);
            Bh[kp * B_STR + n]  = h;
            Blo[kp * B_STR + n] = l;
        }
    }
    __syncthreads();

    const int t  = lane & 3;
    const int g  = lane >> 2;
    const int rb = wid * 32;

    // Accumulators [mtile][ntile][4], seeded with bias
    float acc[2][8][4];
    #pragma unroll
    for (int nt = 0; nt < 8; nt++) {
        float b0 = bl_s[nt * 8 + t * 2];
        float b1 = bl_s[nt * 8 + t * 2 + 1];
        #pragma unroll
        for (int mt = 0; mt < 2; mt++) {
            acc[mt][nt][0] = b0; acc[mt][nt][1] = b1;
            acc[mt][nt][2] = b0; acc[mt][nt][3] = b1;
        }
    }

    #pragma unroll
    for (int kt = 0; kt < 6; kt++) {
        const int kp0 = kt * 8;
        uint32_t ahi[2][4], alo[2][4];
        #pragma unroll
        for (int mt = 0; mt < 2; mt++) {
            const uint32_t* Ah = Ahi + (rb + mt * 16 + g) * A_STR + kp0 + t;
            const uint32_t* Al = Alo + (rb + mt * 16 + g) * A_STR + kp0 + t;
            ahi[mt][0] = Ah[0];                 // (row g,    kp t)
            ahi[mt][1] = Ah[8 * A_STR];         // (row g+8,  kp t)
            ahi[mt][2] = Ah[4];                 // (row g,    kp t+4)
            ahi[mt][3] = Ah[8 * A_STR + 4];     // (row g+8,  kp t+4)
            alo[mt][0] = Al[0];
            alo[mt][1] = Al[8 * A_STR];
            alo[mt][2] = Al[4];
            alo[mt][3] = Al[8 * A_STR + 4];
        }
        #pragma unroll
        for (int nt = 0; nt < 8; nt++) {
            const int n = nt * 8 + g;
            const uint32_t* Bp = Bh  + (kp0 + t) * B_STR + n;
            const uint32_t* Lp = Blo + (kp0 + t) * B_STR + n;
            uint32_t bh[2], blv[2];
            bh[0]  = Bp[0];
            bh[1]  = Bp[4 * B_STR];
            blv[0] = Lp[0];
            blv[1] = Lp[4 * B_STR];
            mma16(acc[0][nt], ahi[0], bh);
            mma16(acc[0][nt], alo[0], bh);
            mma16(acc[0][nt], ahi[0], blv);
            mma16(acc[1][nt], ahi[1], bh);
            mma16(acc[1][nt], alo[1], bh);
            mma16(acc[1][nt], ahi[1], blv);
        }
    }
    __syncthreads();   // done reading A/B; reuse smem as restage buffer

    // ---- Epilogue: relu + logit dot + restage ----
    #pragma unroll
    for (int mt = 0; mt < 2; mt++) {
        #pragma unroll
        for (int half = 0; half < 2; half++) {
            const int row = rb + mt * 16 + half * 8 + g;
            float* hrow = restage + row * H_STR;
            float partial = 0.f;
            #pragma unroll
            for (int nt = 0; nt < 8; nt++) {
                float h0 = fmaxf(acc[mt][nt][half * 2 + 0], 0.f);
                float h1 = fmaxf(acc[mt][nt][half * 2 + 1], 0.f);
                int col = nt * 8 + t * 2;
                partial += h0 * wout_s[col] + h1 * wout_s[col + 1];
                *(float2*)(hrow + col) = make_float2(h0, h1);
            }
            partial += __shfl_xor_sync(0xffffffffu, partial, 1);
            partial += __shfl_xor_sync(0xffffffffu, partial, 2);
            int r = r0 + row;
            if (t == 0 && r < N_TX) __stcs(out + r, partial + bout[0]);
        }
    }
    __syncthreads();

    // ---- Coalesced tx_x store (streaming: write-once, never re-read) ----
    {
        const int vr = (N_TX - r0 < RBLK) ? (N_TX - r0) : RBLK;
        float4* dst = (float4*)(out + N_TX + (size_t)r0 * 64);
        #pragma unroll
        for (int i = tid; i < RBLK * 16; i += 128) {
            int row = i >> 4, c = i & 15;
            if (row < vr)
                __stcs(dst + row * 16 + c,
                       *(float4*)(restage + row * H_STR + c * 4));
        }
    }
}

// ---------------------------------------------------------------------------
extern "C" void kernel_launch(void* const* d_in, const int* in_sizes, int n_in,
                              void* d_out, int out_size) {
    const float* x_tx     = (const float*)d_in[0];
    const float* x_acc    = (const float*)d_in[1];
    const int*   pays_src = (const int*)d_in[2];
    const int*   pays_dst = (const int*)d_in[3];
    // d_in[4], d_in[5]: rev edges — dead code in reference (h_acc unused)
    const float* Wl_pays  = (const float*)d_in[6];
    const float* bl_pays  = (const float*)d_in[7];
    const float* Wr_pays  = (const float*)d_in[8];
    // d_in[9..11]: rev weights — unused
    const float* W_out    = (const float*)d_in[12];
    const float* b_out    = (const float*)d_in[13];
    float* out = (float*)d_out;   // [logits(500000) | tx_x(500000*64)]

    cudaFuncSetAttribute(compute_kernel,
                         cudaFuncAttributeMaxDynamicSharedMemorySize, SMEM_BYTES);

    zero_kernel<<<(N_TX + 255) / 256, 256>>>();
    hist_kernel<<<(NE + 255) / 256, 256>>>(pays_dst);
    scan1_kernel<<<N_SCAN_BLKS, SCAN_BS>>>();
    scan2_kernel<<<1, SCAN_BS>>>();
    place_kernel<<<(NE + 255) / 256, 256>>>(pays_src, pays_dst);
    compute_kernel<<<(N_TX + RBLK - 1) / RBLK, RBLK, SMEM_BYTES>>>(
        x_tx, x_acc, Wl_pays, bl_pays, Wr_pays, W_out, b_out, out);
}